// round 7
// baseline (speedup 1.0000x reference)
#include <cuda_runtime.h>

// ============================================================================
// QuantumNAT: 4-qubit circuit, B=524288.  SINGLE FUSED PERSISTENT KERNEL.
// out_q(x) = sum_{t in {1,cos,sin}^4} D_q[t] * prod_i basis_i[t_i]
// Every block computes the 81 float4 coefficients D from weights in SMEM
// (cheap, redundant), then grid-strides over sample-pairs, 2 samples/thread
// per iteration with packed f32x2 FMAs against broadcast LDS.128 coefs.
//
// Register discipline (hard-learned):
//   R5: cap 64  -> main loop spilled packed arrays to local  -> 114 us.
//   R6: uncapped -> ptxas took 255 regs -> 1 block/SM, occ 12% -> 49 us.
//   R7: cap 84 (launch_bounds(256,3)); main loop needs ~66 regs (R4) so no
//       spill; prep's register hot spot moved into SMEM (colS) so any
//       residual prep spill is one-time noise.
// grid = 444 = 148 SMs x 3 blocks -> exactly one wave.
// ============================================================================

#define NBLOCKS 444
#define NTHREADS 256
#define STRIDE (NBLOCKS * NTHREADS)

// ---------------- complex helpers (prep phase) ----------------
__device__ __forceinline__ float2 cmul(float2 a, float2 b) {
    return make_float2(a.x * b.x - a.y * b.y, a.x * b.y + a.y * b.x);
}
__device__ __forceinline__ float2 cmulcj(float2 a, float2 b) {  // conj(a)*b
    return make_float2(a.x * b.x + a.y * b.y, a.x * b.y - a.y * b.x);
}
__device__ __forceinline__ float2 cadd(float2 a, float2 b) {
    return make_float2(a.x + b.x, a.y + b.y);
}
__device__ __forceinline__ float2 csub(float2 a, float2 b) {
    return make_float2(a.x - b.x, a.y - b.y);
}
__device__ __forceinline__ float2 ctr(float2 x00, float2 x01, float2 x10, float2 x11, int tsel) {
    if (tsel == 0) return make_float2(0.5f * (x00.x + x11.x), 0.5f * (x00.y + x11.y));
    if (tsel == 1) return make_float2(0.5f * (x00.x - x11.x), 0.5f * (x00.y - x11.y));
    return make_float2(0.5f * (x01.y - x10.y), 0.5f * (x10.x - x01.x));
}

// ---------------- packed f32x2 helpers ----------------
__device__ __forceinline__ unsigned long long pk(float a, float b) {
    unsigned long long r;
    asm("mov.b64 %0, {%1, %2};" : "=l"(r) : "f"(a), "f"(b));
    return r;
}
__device__ __forceinline__ void upk(float& a, float& b, unsigned long long v) {
    asm("mov.b64 {%0, %1}, %2;" : "=f"(a), "=f"(b) : "l"(v));
}
__device__ __forceinline__ unsigned long long m2(unsigned long long a, unsigned long long b) {
    unsigned long long r;
    asm("mul.rn.f32x2 %0, %1, %2;" : "=l"(r) : "l"(a), "l"(b));
    return r;
}
__device__ __forceinline__ unsigned long long f2(unsigned long long a, unsigned long long b,
                                                 unsigned long long c) {
    unsigned long long r;
    asm("fma.rn.f32x2 %0, %1, %2, %3;" : "=l"(r) : "l"(a), "l"(b), "l"(c));
    return r;
}

__global__ __launch_bounds__(NTHREADS, 3)
void qnat_fused(const float4* __restrict__ x, float4* __restrict__ out,
                const float* __restrict__ w, int nPairs)
{
    // ---------- shared memory ----------
    __shared__ float2 Ug[12][2][2];
    __shared__ float2 colS[16][17];          // W columns, built in SMEM (pad 17 vs conflicts)
    __shared__ float2 Wm[16][16];
    __shared__ float2 Mq[4][16][16];
    __shared__ float2 T3[4][3][8][8];
    __shared__ float2 T2s[4][3][3][4][4];
    __shared__ float2 T1s[4][3][3][3][2][2];
    __shared__ ulonglong2 sc[81];            // final {D0,D1},{D2,D3}

    const int t = threadIdx.x;

    // ======================= PREP PHASE (per block) =======================
    // --- 1. fused gate matrices U = RZ*RY*RX ------------------------------
    if (t < 12) {
        float ax = 0.5f * w[t * 3 + 0];
        float ay = 0.5f * w[t * 3 + 1];
        float az = 0.5f * w[t * 3 + 2];
        float sx = sinf(ax), cx = cosf(ax);
        float sy = sinf(ay), cy = cosf(ay);
        float sz = sinf(az), cz = cosf(az);
        float2 a00 = make_float2( cy * cx,  sy * sx);
        float2 a01 = make_float2(-sy * cx, -cy * sx);
        float2 a10 = make_float2( sy * cx, -cy * sx);
        float2 a11 = make_float2( cy * cx, -sy * sx);
        float2 e0 = make_float2(cz, -sz);
        float2 e1 = make_float2(cz,  sz);
        Ug[t][0][0] = cmul(e0, a00); Ug[t][0][1] = cmul(e0, a01);
        Ug[t][1][0] = cmul(e1, a10); Ug[t][1][1] = cmul(e1, a11);
    }
    __syncthreads();

    // --- 2. W columns (built in SMEM; thread t owns column t) -------------
    if (t < 16) {
        #pragma unroll
        for (int m = 0; m < 16; m++) colS[t][m] = make_float2((m == t) ? 1.0f : 0.0f, 0.0f);

        #pragma unroll 1
        for (int l = 0; l < 3; l++) {
            #pragma unroll
            for (int i = 0; i < 4; i++) {
                float2 u00 = Ug[l * 4 + i][0][0], u01 = Ug[l * 4 + i][0][1];
                float2 u10 = Ug[l * 4 + i][1][0], u11 = Ug[l * 4 + i][1][1];
                const int str = 1 << (3 - i);
                #pragma unroll
                for (int p = 0; p < 8; p++) {
                    const int low = p & (str - 1);
                    const int m0  = ((p - low) << 1) | low;
                    const int m1  = m0 | str;
                    float2 a = colS[t][m0], b = colS[t][m1];
                    colS[t][m0] = cadd(cmul(u00, a), cmul(u01, b));
                    colS[t][m1] = cadd(cmul(u10, a), cmul(u11, b));
                }
            }
            // CNOT chain: control i -> target i+1 (swap rows)
            #pragma unroll
            for (int i = 0; i < 3; i++) {
                const int cmask = 1 << (3 - i);
                const int tmask = 1 << (2 - i);
                #pragma unroll
                for (int m = 0; m < 16; m++) {
                    if ((m & cmask) && !(m & tmask)) {
                        float2 tmp = colS[t][m];
                        colS[t][m] = colS[t][m | tmask];
                        colS[t][m | tmask] = tmp;
                    }
                }
            }
        }
    }
    __syncthreads();
    // transpose into Wm[m][col]
    if (t < 256) {
        const int m = t >> 4, c = t & 15;
        Wm[m][c] = colS[c][m];
    }
    __syncthreads();

    // --- 3. M_q = W^dag Z_q W ----------------------------------------------
    {
        const int j = t >> 4, k = t & 15;
        float2 a0 = make_float2(0.f, 0.f), a1 = a0, a2 = a0, a3 = a0;
        #pragma unroll
        for (int m = 0; m < 16; m++) {
            float2 p = cmulcj(Wm[m][j], Wm[m][k]);
            a0 = (m & 8) ? csub(a0, p) : cadd(a0, p);
            a1 = (m & 4) ? csub(a1, p) : cadd(a1, p);
            a2 = (m & 2) ? csub(a2, p) : cadd(a2, p);
            a3 = (m & 1) ? csub(a3, p) : cadd(a3, p);
        }
        Mq[0][j][k] = a0; Mq[1][j][k] = a1; Mq[2][j][k] = a2; Mq[3][j][k] = a3;
    }
    __syncthreads();

    // --- 4a..4d staged contractions ----------------------------------------
    for (int e = t; e < 768; e += NTHREADS) {
        const int q = e / 192, r = e % 192, t3 = r / 64, ab = r % 64;
        const int a = ab >> 3, b = ab & 7;
        T3[q][t3][a][b] = ctr(Mq[q][2 * a][2 * b],     Mq[q][2 * a][2 * b + 1],
                              Mq[q][2 * a + 1][2 * b], Mq[q][2 * a + 1][2 * b + 1], t3);
    }
    __syncthreads();

    for (int e = t; e < 576; e += NTHREADS) {
        const int q = e / 144, r = e % 144, t2 = r / 48, r2 = r % 48;
        const int t3 = r2 / 16, ab = r2 % 16, a = ab >> 2, b = ab & 3;
        T2s[q][t2][t3][a][b] = ctr(T3[q][t3][2 * a][2 * b],     T3[q][t3][2 * a][2 * b + 1],
                                   T3[q][t3][2 * a + 1][2 * b], T3[q][t3][2 * a + 1][2 * b + 1], t2);
    }
    __syncthreads();

    for (int e = t; e < 432; e += NTHREADS) {
        const int q = e / 108, r = e % 108, t1 = r / 36, r2 = r % 36;
        const int t2 = r2 / 12, r3 = r2 % 12, t3 = r3 / 4, ab = r3 & 3;
        const int a = ab >> 1, b = ab & 1;
        T1s[q][t1][t2][t3][a][b] = ctr(T2s[q][t2][t3][2 * a][2 * b],     T2s[q][t2][t3][2 * a][2 * b + 1],
                                       T2s[q][t2][t3][2 * a + 1][2 * b], T2s[q][t2][t3][2 * a + 1][2 * b + 1], t1);
    }
    __syncthreads();

    for (int e = t; e < 324; e += NTHREADS) {
        const int q = e / 81, tt = e % 81;
        const int t0 = tt / 27, r = tt % 27, t1 = r / 9, r2 = r % 9, t2 = r2 / 3, t3 = r2 % 3;
        float2 x00 = T1s[q][t1][t2][t3][0][0];
        float2 x01 = T1s[q][t1][t2][t3][0][1];
        float2 x10 = T1s[q][t1][t2][t3][1][0];
        float2 x11 = T1s[q][t1][t2][t3][1][1];
        float d;
        if (t0 == 0)      d = 0.5f * (x00.x + x11.x);
        else if (t0 == 1) d = 0.5f * (x00.x - x11.x);
        else              d = 0.5f * (x01.y - x10.y);
        reinterpret_cast<float*>(sc)[tt * 4 + q] = d;
    }
    __syncthreads();

    // ======================= MAIN PHASE (grid-stride) ======================
    for (int gid = blockIdx.x * NTHREADS + t; gid < nPairs; gid += STRIDE) {
        const float4 xa = x[2 * gid];
        const float4 xb = x[2 * gid + 1];

        float sA0, cA0, sA1, cA1, sA2, cA2, sA3, cA3;
        float sB0, cB0, sB1, cB1, sB2, cB2, sB3, cB3;
        __sincosf(xa.x, &sA0, &cA0);  __sincosf(xb.x, &sB0, &cB0);
        __sincosf(xa.y, &sA1, &cA1);  __sincosf(xb.y, &sB1, &cB1);
        __sincosf(xa.z, &sA2, &cA2);  __sincosf(xb.z, &sB2, &cB2);
        __sincosf(xa.w, &sA3, &cA3);  __sincosf(xb.w, &sB3, &cB3);

        const unsigned long long cA0d = pk(cA0, cA0), sA0d = pk(sA0, sA0);
        const unsigned long long cA1d = pk(cA1, cA1), sA1d = pk(sA1, sA1);
        const unsigned long long cA2d = pk(cA2, cA2), sA2d = pk(sA2, sA2);
        const unsigned long long cA3d = pk(cA3, cA3), sA3d = pk(sA3, sA3);
        const unsigned long long cB0d = pk(cB0, cB0), sB0d = pk(sB0, sB0);
        const unsigned long long cB1d = pk(cB1, cB1), sB1d = pk(sB1, sB1);
        const unsigned long long cB2d = pk(cB2, cB2), sB2d = pk(sB2, sB2);
        const unsigned long long cB3d = pk(cB3, cB3), sB3d = pk(sB3, sB3);

        unsigned long long bA[9], bB[9];
        bA[1] = cA3d; bA[2] = sA3d; bA[3] = cA2d;
        bA[4] = m2(cA2d, cA3d); bA[5] = m2(cA2d, sA3d);
        bA[6] = sA2d; bA[7] = m2(sA2d, cA3d); bA[8] = m2(sA2d, sA3d);
        bB[1] = cB3d; bB[2] = sB3d; bB[3] = cB2d;
        bB[4] = m2(cB2d, cB3d); bB[5] = m2(cB2d, sB3d);
        bB[6] = sB2d; bB[7] = m2(sB2d, cB3d); bB[8] = m2(sB2d, sB3d);

        unsigned long long aA01 = 0, aA23 = 0, aB01 = 0, aB23 = 0;

        #pragma unroll
        for (int j = 0; j < 9; j++) {
            ulonglong2 cv0 = sc[j * 9];
            unsigned long long iA01 = cv0.x, iA23 = cv0.y;
            unsigned long long iB01 = cv0.x, iB23 = cv0.y;
            #pragma unroll
            for (int k = 1; k < 9; k++) {
                const ulonglong2 cv = sc[j * 9 + k];
                iA01 = f2(cv.x, bA[k], iA01);
                iA23 = f2(cv.y, bA[k], iA23);
                iB01 = f2(cv.x, bB[k], iB01);
                iB23 = f2(cv.y, bB[k], iB23);
            }
            if (j == 0) {
                aA01 = iA01; aA23 = iA23; aB01 = iB01; aB23 = iB23;
            } else {
                unsigned long long bjA, bjB;
                switch (j) {
                    case 1: bjA = cA1d;            bjB = cB1d;            break;
                    case 2: bjA = sA1d;            bjB = sB1d;            break;
                    case 3: bjA = cA0d;            bjB = cB0d;            break;
                    case 4: bjA = m2(cA0d, cA1d);  bjB = m2(cB0d, cB1d);  break;
                    case 5: bjA = m2(cA0d, sA1d);  bjB = m2(cB0d, sB1d);  break;
                    case 6: bjA = sA0d;            bjB = sB0d;            break;
                    case 7: bjA = m2(sA0d, cA1d);  bjB = m2(sB0d, cB1d);  break;
                    default: bjA = m2(sA0d, sA1d); bjB = m2(sB0d, sB1d);  break;
                }
                aA01 = f2(bjA, iA01, aA01);
                aA23 = f2(bjA, iA23, aA23);
                aB01 = f2(bjB, iB01, aB01);
                aB23 = f2(bjB, iB23, aB23);
            }
        }

        float4 oa, ob;
        upk(oa.x, oa.y, aA01); upk(oa.z, oa.w, aA23);
        upk(ob.x, ob.y, aB01); upk(ob.z, ob.w, aB23);
        out[2 * gid]     = oa;
        out[2 * gid + 1] = ob;
    }
}

// ============================================================================
extern "C" void kernel_launch(void* const* d_in, const int* in_sizes, int n_in,
                              void* d_out, int out_size)
{
    const float* x = (const float*)d_in[0];        // [B,4] float32
    const float* w = (const float*)d_in[1];        // [3,4,3] float32

    const int B = in_sizes[0] / 4;                 // 524288
    const int nPairs = B / 2;                      // 262144

    qnat_fused<<<NBLOCKS, NTHREADS>>>((const float4*)x, (float4*)d_out, w, nPairs);
}

// round 8
// speedup vs baseline: 1.4631x; 1.4631x over previous
#include <cuda_runtime.h>

// ============================================================================
// QuantumNAT: 4-qubit circuit, B=524288.  TWO KERNELS (fusion abandoned:
// R5/R6/R7 showed whole-kernel regalloc of prep+main either spills the hot
// loop or takes 255 regs).
// out_q(x) = sum_{t in {1,cos,sin}^4} D_q[t] * prod_i basis_i[t_i]
// prep_kernel: 1 block, computes D[81] as float4{D0,D1,D2,D3} -> g_coefStage.
// qnat_main:   ONE sample per thread, f32x2 packing across the two OUTPUT
//              pairs {o0,o1},{o2,o3}; ~48 regs -> 4 blocks/SM (occ 67%).
//              Persistent grid 592 = 148 x 4, grid-stride.
// ============================================================================

#define NBLOCKS 592
#define NTHREADS 256
#define STRIDE (NBLOCKS * NTHREADS)

__device__ float4 g_coefStage[81];

// ---------------- complex helpers (prep only) ----------------
__device__ __forceinline__ float2 cmul(float2 a, float2 b) {
    return make_float2(a.x * b.x - a.y * b.y, a.x * b.y + a.y * b.x);
}
__device__ __forceinline__ float2 cmulcj(float2 a, float2 b) {  // conj(a)*b
    return make_float2(a.x * b.x + a.y * b.y, a.x * b.y - a.y * b.x);
}
__device__ __forceinline__ float2 cadd(float2 a, float2 b) {
    return make_float2(a.x + b.x, a.y + b.y);
}
__device__ __forceinline__ float2 csub(float2 a, float2 b) {
    return make_float2(a.x - b.x, a.y - b.y);
}
__device__ __forceinline__ float2 ctr(float2 x00, float2 x01, float2 x10, float2 x11, int tsel) {
    if (tsel == 0) return make_float2(0.5f * (x00.x + x11.x), 0.5f * (x00.y + x11.y));
    if (tsel == 1) return make_float2(0.5f * (x00.x - x11.x), 0.5f * (x00.y - x11.y));
    return make_float2(0.5f * (x01.y - x10.y), 0.5f * (x10.x - x01.x));
}

// ============================================================================
// Prep kernel: one block, 256 threads (identical math to R2/R4).
// ============================================================================
__global__ void prep_kernel(const float* __restrict__ w)
{
    __shared__ float2 Ug[12][2][2];
    __shared__ float2 Wm[16][16];
    __shared__ float2 Mq[4][16][16];
    __shared__ float2 T3[4][3][8][8];
    __shared__ float2 T2s[4][3][3][4][4];
    __shared__ float2 T1s[4][3][3][3][2][2];

    const int t = threadIdx.x;

    if (t < 12) {
        float ax = 0.5f * w[t * 3 + 0];
        float ay = 0.5f * w[t * 3 + 1];
        float az = 0.5f * w[t * 3 + 2];
        float sx = sinf(ax), cx = cosf(ax);
        float sy = sinf(ay), cy = cosf(ay);
        float sz = sinf(az), cz = cosf(az);
        float2 a00 = make_float2( cy * cx,  sy * sx);
        float2 a01 = make_float2(-sy * cx, -cy * sx);
        float2 a10 = make_float2( sy * cx, -cy * sx);
        float2 a11 = make_float2( cy * cx, -sy * sx);
        float2 e0 = make_float2(cz, -sz);
        float2 e1 = make_float2(cz,  sz);
        Ug[t][0][0] = cmul(e0, a00); Ug[t][0][1] = cmul(e0, a01);
        Ug[t][1][0] = cmul(e1, a10); Ug[t][1][1] = cmul(e1, a11);
    }
    __syncthreads();

    if (t < 16) {
        float2 col[16];
        #pragma unroll
        for (int m = 0; m < 16; m++) col[m] = make_float2((m == t) ? 1.0f : 0.0f, 0.0f);

        #pragma unroll
        for (int l = 0; l < 3; l++) {
            #pragma unroll
            for (int i = 0; i < 4; i++) {
                float2 u00 = Ug[l * 4 + i][0][0], u01 = Ug[l * 4 + i][0][1];
                float2 u10 = Ug[l * 4 + i][1][0], u11 = Ug[l * 4 + i][1][1];
                const int str = 1 << (3 - i);
                #pragma unroll
                for (int p = 0; p < 8; p++) {
                    const int low = p & (str - 1);
                    const int m0  = ((p - low) << 1) | low;
                    const int m1  = m0 | str;
                    float2 a = col[m0], b = col[m1];
                    col[m0] = cadd(cmul(u00, a), cmul(u01, b));
                    col[m1] = cadd(cmul(u10, a), cmul(u11, b));
                }
            }
            #pragma unroll
            for (int i = 0; i < 3; i++) {
                const int cmask = 1 << (3 - i);
                const int tmask = 1 << (2 - i);
                #pragma unroll
                for (int m = 0; m < 16; m++) {
                    if ((m & cmask) && !(m & tmask)) {
                        float2 tmp = col[m];
                        col[m] = col[m | tmask];
                        col[m | tmask] = tmp;
                    }
                }
            }
        }
        #pragma unroll
        for (int m = 0; m < 16; m++) Wm[m][t] = col[m];
    }
    __syncthreads();

    {
        const int j = t >> 4, k = t & 15;
        float2 a0 = make_float2(0.f, 0.f), a1 = a0, a2 = a0, a3 = a0;
        #pragma unroll
        for (int m = 0; m < 16; m++) {
            float2 p = cmulcj(Wm[m][j], Wm[m][k]);
            a0 = (m & 8) ? csub(a0, p) : cadd(a0, p);
            a1 = (m & 4) ? csub(a1, p) : cadd(a1, p);
            a2 = (m & 2) ? csub(a2, p) : cadd(a2, p);
            a3 = (m & 1) ? csub(a3, p) : cadd(a3, p);
        }
        Mq[0][j][k] = a0; Mq[1][j][k] = a1; Mq[2][j][k] = a2; Mq[3][j][k] = a3;
    }
    __syncthreads();

    for (int e = t; e < 768; e += NTHREADS) {
        const int q = e / 192, r = e % 192, t3 = r / 64, ab = r % 64;
        const int a = ab >> 3, b = ab & 7;
        T3[q][t3][a][b] = ctr(Mq[q][2 * a][2 * b],     Mq[q][2 * a][2 * b + 1],
                              Mq[q][2 * a + 1][2 * b], Mq[q][2 * a + 1][2 * b + 1], t3);
    }
    __syncthreads();

    for (int e = t; e < 576; e += NTHREADS) {
        const int q = e / 144, r = e % 144, t2 = r / 48, r2 = r % 48;
        const int t3 = r2 / 16, ab = r2 % 16, a = ab >> 2, b = ab & 3;
        T2s[q][t2][t3][a][b] = ctr(T3[q][t3][2 * a][2 * b],     T3[q][t3][2 * a][2 * b + 1],
                                   T3[q][t3][2 * a + 1][2 * b], T3[q][t3][2 * a + 1][2 * b + 1], t2);
    }
    __syncthreads();

    for (int e = t; e < 432; e += NTHREADS) {
        const int q = e / 108, r = e % 108, t1 = r / 36, r2 = r % 36;
        const int t2 = r2 / 12, r3 = r2 % 12, t3 = r3 / 4, ab = r3 & 3;
        const int a = ab >> 1, b = ab & 1;
        T1s[q][t1][t2][t3][a][b] = ctr(T2s[q][t2][t3][2 * a][2 * b],     T2s[q][t2][t3][2 * a][2 * b + 1],
                                       T2s[q][t2][t3][2 * a + 1][2 * b], T2s[q][t2][t3][2 * a + 1][2 * b + 1], t1);
    }
    __syncthreads();

    for (int e = t; e < 324; e += NTHREADS) {
        const int q = e / 81, tt = e % 81;
        const int t0 = tt / 27, r = tt % 27, t1 = r / 9, r2 = r % 9, t2 = r2 / 3, t3 = r2 % 3;
        float2 x00 = T1s[q][t1][t2][t3][0][0];
        float2 x01 = T1s[q][t1][t2][t3][0][1];
        float2 x10 = T1s[q][t1][t2][t3][1][0];
        float2 x11 = T1s[q][t1][t2][t3][1][1];
        float d;
        if (t0 == 0)      d = 0.5f * (x00.x + x11.x);
        else if (t0 == 1) d = 0.5f * (x00.x - x11.x);
        else              d = 0.5f * (x01.y - x10.y);
        reinterpret_cast<float*>(g_coefStage)[tt * 4 + q] = d;
    }
}

// ---------------- packed f32x2 helpers ----------------
__device__ __forceinline__ unsigned long long pk(float a, float b) {
    unsigned long long r;
    asm("mov.b64 %0, {%1, %2};" : "=l"(r) : "f"(a), "f"(b));
    return r;
}
__device__ __forceinline__ void upk(float& a, float& b, unsigned long long v) {
    asm("mov.b64 {%0, %1}, %2;" : "=f"(a), "=f"(b) : "l"(v));
}
__device__ __forceinline__ unsigned long long m2(unsigned long long a, unsigned long long b) {
    unsigned long long r;
    asm("mul.rn.f32x2 %0, %1, %2;" : "=l"(r) : "l"(a), "l"(b));
    return r;
}
__device__ __forceinline__ unsigned long long f2(unsigned long long a, unsigned long long b,
                                                 unsigned long long c) {
    unsigned long long r;
    asm("fma.rn.f32x2 %0, %1, %2, %3;" : "=l"(r) : "l"(a), "l"(b), "l"(c));
    return r;
}

// ============================================================================
// Main kernel: ONE sample per thread; outputs packed {o0,o1},{o2,o3}.
// ============================================================================
__global__ __launch_bounds__(NTHREADS, 4)
void qnat_main(const float4* __restrict__ x, float4* __restrict__ out, int n)
{
    __shared__ ulonglong2 sc[81];   // {D0,D1},{D2,D3} per t-index
    if (threadIdx.x < 81)
        sc[threadIdx.x] = reinterpret_cast<const ulonglong2*>(g_coefStage)[threadIdx.x];
    __syncthreads();

    for (int gid = blockIdx.x * NTHREADS + threadIdx.x; gid < n; gid += STRIDE) {
        const float4 xv = x[gid];

        float s0, c0, s1, c1, s2, c2, s3, c3;
        __sincosf(xv.x, &s0, &c0);
        __sincosf(xv.y, &s1, &c1);
        __sincosf(xv.z, &s2, &c2);
        __sincosf(xv.w, &s3, &c3);

        // duplicated packed values
        const unsigned long long c0d = pk(c0, c0), s0d = pk(s0, s0);
        const unsigned long long c1d = pk(c1, c1), s1d = pk(s1, s1);
        const unsigned long long c2d = pk(c2, c2), s2d = pk(s2, s2);
        const unsigned long long c3d = pk(c3, c3), s3d = pk(s3, s3);

        // b23 basis (qubits 2,3), duplicated. Index k = t2*3 + t3 (k=0 is 1).
        unsigned long long b[9];
        b[1] = c3d; b[2] = s3d; b[3] = c2d;
        b[4] = m2(c2d, c3d); b[5] = m2(c2d, s3d);
        b[6] = s2d; b[7] = m2(s2d, c3d); b[8] = m2(s2d, s3d);

        unsigned long long a01 = 0, a23 = 0;

        #pragma unroll
        for (int j = 0; j < 9; j++) {
            ulonglong2 cv0 = sc[j * 9];
            unsigned long long i01 = cv0.x, i23 = cv0.y;
            #pragma unroll
            for (int k = 1; k < 9; k++) {
                const ulonglong2 cv = sc[j * 9 + k];
                i01 = f2(cv.x, b[k], i01);
                i23 = f2(cv.y, b[k], i23);
            }
            if (j == 0) {
                a01 = i01; a23 = i23;
            } else {
                unsigned long long bj;
                switch (j) {
                    case 1: bj = c1d;           break;
                    case 2: bj = s1d;           break;
                    case 3: bj = c0d;           break;
                    case 4: bj = m2(c0d, c1d);  break;
                    case 5: bj = m2(c0d, s1d);  break;
                    case 6: bj = s0d;           break;
                    case 7: bj = m2(s0d, c1d);  break;
                    default: bj = m2(s0d, s1d); break;
                }
                a01 = f2(bj, i01, a01);
                a23 = f2(bj, i23, a23);
            }
        }

        float4 o;
        upk(o.x, o.y, a01);
        upk(o.z, o.w, a23);
        out[gid] = o;
    }
}

// ============================================================================
extern "C" void kernel_launch(void* const* d_in, const int* in_sizes, int n_in,
                              void* d_out, int out_size)
{
    const float* x = (const float*)d_in[0];        // [B,4] float32
    const float* w = (const float*)d_in[1];        // [3,4,3] float32

    const int B = in_sizes[0] / 4;                 // 524288 samples

    prep_kernel<<<1, NTHREADS>>>(w);
    qnat_main<<<NBLOCKS, NTHREADS>>>((const float4*)x, (float4*)d_out, B);
}

// round 9
// speedup vs baseline: 5.4293x; 3.7109x over previous
#include <cuda_runtime.h>

// ============================================================================
// QuantumNAT: 4-qubit circuit, B=524288.  TWO KERNELS.
// out_q(x) = sum_{t in {1,cos,sin}^4} D_q[t] * prod_i basis_i[t_i]
// prep_kernel: 1 block, computes D[81] as float4{D0,D1,D2,D3} -> g_coefStage.
// qnat_main:   R4-proven body (2 samples/thread, packed f32x2, SMEM coefs,
//              NO register cap -> ~66 regs, no spill), now persistent:
//              grid 444 = 148 x 3 blocks/SM, grid-stride (2-3 pairs/thread).
// Register lessons: cap 64 spills (R5/R8), cap 84 spills when fused (R7),
// uncapped fused balloons to 255 (R6). Natural allocation of THIS main body
// is 66 regs (R4) -> 3 blocks/SM, stable.
// ============================================================================

#define NBLOCKS 444
#define NTHREADS 256
#define STRIDE (NBLOCKS * NTHREADS)

__device__ float4 g_coefStage[81];

// ---------------- complex helpers (prep only) ----------------
__device__ __forceinline__ float2 cmul(float2 a, float2 b) {
    return make_float2(a.x * b.x - a.y * b.y, a.x * b.y + a.y * b.x);
}
__device__ __forceinline__ float2 cmulcj(float2 a, float2 b) {  // conj(a)*b
    return make_float2(a.x * b.x + a.y * b.y, a.x * b.y - a.y * b.x);
}
__device__ __forceinline__ float2 cadd(float2 a, float2 b) {
    return make_float2(a.x + b.x, a.y + b.y);
}
__device__ __forceinline__ float2 csub(float2 a, float2 b) {
    return make_float2(a.x - b.x, a.y - b.y);
}
__device__ __forceinline__ float2 ctr(float2 x00, float2 x01, float2 x10, float2 x11, int tsel) {
    if (tsel == 0) return make_float2(0.5f * (x00.x + x11.x), 0.5f * (x00.y + x11.y));
    if (tsel == 1) return make_float2(0.5f * (x00.x - x11.x), 0.5f * (x00.y - x11.y));
    return make_float2(0.5f * (x01.y - x10.y), 0.5f * (x10.x - x01.x));
}

// ============================================================================
// Prep kernel: one block, 256 threads (identical math to R2/R4).
// ============================================================================
__global__ void prep_kernel(const float* __restrict__ w)
{
    __shared__ float2 Ug[12][2][2];
    __shared__ float2 Wm[16][16];
    __shared__ float2 Mq[4][16][16];
    __shared__ float2 T3[4][3][8][8];
    __shared__ float2 T2s[4][3][3][4][4];
    __shared__ float2 T1s[4][3][3][3][2][2];

    const int t = threadIdx.x;

    if (t < 12) {
        float ax = 0.5f * w[t * 3 + 0];
        float ay = 0.5f * w[t * 3 + 1];
        float az = 0.5f * w[t * 3 + 2];
        float sx = sinf(ax), cx = cosf(ax);
        float sy = sinf(ay), cy = cosf(ay);
        float sz = sinf(az), cz = cosf(az);
        float2 a00 = make_float2( cy * cx,  sy * sx);
        float2 a01 = make_float2(-sy * cx, -cy * sx);
        float2 a10 = make_float2( sy * cx, -cy * sx);
        float2 a11 = make_float2( cy * cx, -sy * sx);
        float2 e0 = make_float2(cz, -sz);
        float2 e1 = make_float2(cz,  sz);
        Ug[t][0][0] = cmul(e0, a00); Ug[t][0][1] = cmul(e0, a01);
        Ug[t][1][0] = cmul(e1, a10); Ug[t][1][1] = cmul(e1, a11);
    }
    __syncthreads();

    if (t < 16) {
        float2 col[16];
        #pragma unroll
        for (int m = 0; m < 16; m++) col[m] = make_float2((m == t) ? 1.0f : 0.0f, 0.0f);

        #pragma unroll
        for (int l = 0; l < 3; l++) {
            #pragma unroll
            for (int i = 0; i < 4; i++) {
                float2 u00 = Ug[l * 4 + i][0][0], u01 = Ug[l * 4 + i][0][1];
                float2 u10 = Ug[l * 4 + i][1][0], u11 = Ug[l * 4 + i][1][1];
                const int str = 1 << (3 - i);
                #pragma unroll
                for (int p = 0; p < 8; p++) {
                    const int low = p & (str - 1);
                    const int m0  = ((p - low) << 1) | low;
                    const int m1  = m0 | str;
                    float2 a = col[m0], b = col[m1];
                    col[m0] = cadd(cmul(u00, a), cmul(u01, b));
                    col[m1] = cadd(cmul(u10, a), cmul(u11, b));
                }
            }
            #pragma unroll
            for (int i = 0; i < 3; i++) {
                const int cmask = 1 << (3 - i);
                const int tmask = 1 << (2 - i);
                #pragma unroll
                for (int m = 0; m < 16; m++) {
                    if ((m & cmask) && !(m & tmask)) {
                        float2 tmp = col[m];
                        col[m] = col[m | tmask];
                        col[m | tmask] = tmp;
                    }
                }
            }
        }
        #pragma unroll
        for (int m = 0; m < 16; m++) Wm[m][t] = col[m];
    }
    __syncthreads();

    {
        const int j = t >> 4, k = t & 15;
        float2 a0 = make_float2(0.f, 0.f), a1 = a0, a2 = a0, a3 = a0;
        #pragma unroll
        for (int m = 0; m < 16; m++) {
            float2 p = cmulcj(Wm[m][j], Wm[m][k]);
            a0 = (m & 8) ? csub(a0, p) : cadd(a0, p);
            a1 = (m & 4) ? csub(a1, p) : cadd(a1, p);
            a2 = (m & 2) ? csub(a2, p) : cadd(a2, p);
            a3 = (m & 1) ? csub(a3, p) : cadd(a3, p);
        }
        Mq[0][j][k] = a0; Mq[1][j][k] = a1; Mq[2][j][k] = a2; Mq[3][j][k] = a3;
    }
    __syncthreads();

    for (int e = t; e < 768; e += NTHREADS) {
        const int q = e / 192, r = e % 192, t3 = r / 64, ab = r % 64;
        const int a = ab >> 3, b = ab & 7;
        T3[q][t3][a][b] = ctr(Mq[q][2 * a][2 * b],     Mq[q][2 * a][2 * b + 1],
                              Mq[q][2 * a + 1][2 * b], Mq[q][2 * a + 1][2 * b + 1], t3);
    }
    __syncthreads();

    for (int e = t; e < 576; e += NTHREADS) {
        const int q = e / 144, r = e % 144, t2 = r / 48, r2 = r % 48;
        const int t3 = r2 / 16, ab = r2 % 16, a = ab >> 2, b = ab & 3;
        T2s[q][t2][t3][a][b] = ctr(T3[q][t3][2 * a][2 * b],     T3[q][t3][2 * a][2 * b + 1],
                                   T3[q][t3][2 * a + 1][2 * b], T3[q][t3][2 * a + 1][2 * b + 1], t2);
    }
    __syncthreads();

    for (int e = t; e < 432; e += NTHREADS) {
        const int q = e / 108, r = e % 108, t1 = r / 36, r2 = r % 36;
        const int t2 = r2 / 12, r3 = r2 % 12, t3 = r3 / 4, ab = r3 & 3;
        const int a = ab >> 1, b = ab & 1;
        T1s[q][t1][t2][t3][a][b] = ctr(T2s[q][t2][t3][2 * a][2 * b],     T2s[q][t2][t3][2 * a][2 * b + 1],
                                       T2s[q][t2][t3][2 * a + 1][2 * b], T2s[q][t2][t3][2 * a + 1][2 * b + 1], t1);
    }
    __syncthreads();

    for (int e = t; e < 324; e += NTHREADS) {
        const int q = e / 81, tt = e % 81;
        const int t0 = tt / 27, r = tt % 27, t1 = r / 9, r2 = r % 9, t2 = r2 / 3, t3 = r2 % 3;
        float2 x00 = T1s[q][t1][t2][t3][0][0];
        float2 x01 = T1s[q][t1][t2][t3][0][1];
        float2 x10 = T1s[q][t1][t2][t3][1][0];
        float2 x11 = T1s[q][t1][t2][t3][1][1];
        float d;
        if (t0 == 0)      d = 0.5f * (x00.x + x11.x);
        else if (t0 == 1) d = 0.5f * (x00.x - x11.x);
        else              d = 0.5f * (x01.y - x10.y);
        reinterpret_cast<float*>(g_coefStage)[tt * 4 + q] = d;
    }
}

// ---------------- packed f32x2 helpers ----------------
__device__ __forceinline__ unsigned long long pk(float a, float b) {
    unsigned long long r;
    asm("mov.b64 %0, {%1, %2};" : "=l"(r) : "f"(a), "f"(b));
    return r;
}
__device__ __forceinline__ void upk(float& a, float& b, unsigned long long v) {
    asm("mov.b64 {%0, %1}, %2;" : "=f"(a), "=f"(b) : "l"(v));
}
__device__ __forceinline__ unsigned long long m2(unsigned long long a, unsigned long long b) {
    unsigned long long r;
    asm("mul.rn.f32x2 %0, %1, %2;" : "=l"(r) : "l"(a), "l"(b));
    return r;
}
__device__ __forceinline__ unsigned long long f2(unsigned long long a, unsigned long long b,
                                                 unsigned long long c) {
    unsigned long long r;
    asm("fma.rn.f32x2 %0, %1, %2, %3;" : "=l"(r) : "l"(a), "l"(b), "l"(c));
    return r;
}

// ============================================================================
// Main kernel: R4 body, persistent grid-stride. NO min-blocks cap.
// ============================================================================
__global__ __launch_bounds__(NTHREADS)
void qnat_main(const float4* __restrict__ x, float4* __restrict__ out, int nPairs)
{
    __shared__ ulonglong2 sc[81];   // {D0,D1},{D2,D3} per t-index
    if (threadIdx.x < 81)
        sc[threadIdx.x] = reinterpret_cast<const ulonglong2*>(g_coefStage)[threadIdx.x];
    __syncthreads();

    for (int gid = blockIdx.x * NTHREADS + threadIdx.x; gid < nPairs; gid += STRIDE) {
        const float4 xa = x[2 * gid];
        const float4 xb = x[2 * gid + 1];

        float sA0, cA0, sA1, cA1, sA2, cA2, sA3, cA3;
        float sB0, cB0, sB1, cB1, sB2, cB2, sB3, cB3;
        __sincosf(xa.x, &sA0, &cA0);  __sincosf(xb.x, &sB0, &cB0);
        __sincosf(xa.y, &sA1, &cA1);  __sincosf(xb.y, &sB1, &cB1);
        __sincosf(xa.z, &sA2, &cA2);  __sincosf(xb.z, &sB2, &cB2);
        __sincosf(xa.w, &sA3, &cA3);  __sincosf(xb.w, &sB3, &cB3);

        const unsigned long long cA0d = pk(cA0, cA0), sA0d = pk(sA0, sA0);
        const unsigned long long cA1d = pk(cA1, cA1), sA1d = pk(sA1, sA1);
        const unsigned long long cA2d = pk(cA2, cA2), sA2d = pk(sA2, sA2);
        const unsigned long long cA3d = pk(cA3, cA3), sA3d = pk(sA3, sA3);
        const unsigned long long cB0d = pk(cB0, cB0), sB0d = pk(sB0, sB0);
        const unsigned long long cB1d = pk(cB1, cB1), sB1d = pk(sB1, sB1);
        const unsigned long long cB2d = pk(cB2, cB2), sB2d = pk(sB2, sB2);
        const unsigned long long cB3d = pk(cB3, cB3), sB3d = pk(sB3, sB3);

        unsigned long long bA[9], bB[9];
        bA[1] = cA3d; bA[2] = sA3d; bA[3] = cA2d;
        bA[4] = m2(cA2d, cA3d); bA[5] = m2(cA2d, sA3d);
        bA[6] = sA2d; bA[7] = m2(sA2d, cA3d); bA[8] = m2(sA2d, sA3d);
        bB[1] = cB3d; bB[2] = sB3d; bB[3] = cB2d;
        bB[4] = m2(cB2d, cB3d); bB[5] = m2(cB2d, sB3d);
        bB[6] = sB2d; bB[7] = m2(sB2d, cB3d); bB[8] = m2(sB2d, sB3d);

        unsigned long long aA01 = 0, aA23 = 0, aB01 = 0, aB23 = 0;

        #pragma unroll
        for (int j = 0; j < 9; j++) {
            ulonglong2 cv0 = sc[j * 9];
            unsigned long long iA01 = cv0.x, iA23 = cv0.y;
            unsigned long long iB01 = cv0.x, iB23 = cv0.y;
            #pragma unroll
            for (int k = 1; k < 9; k++) {
                const ulonglong2 cv = sc[j * 9 + k];
                iA01 = f2(cv.x, bA[k], iA01);
                iA23 = f2(cv.y, bA[k], iA23);
                iB01 = f2(cv.x, bB[k], iB01);
                iB23 = f2(cv.y, bB[k], iB23);
            }
            if (j == 0) {
                aA01 = iA01; aA23 = iA23; aB01 = iB01; aB23 = iB23;
            } else {
                unsigned long long bjA, bjB;
                switch (j) {
                    case 1: bjA = cA1d;            bjB = cB1d;            break;
                    case 2: bjA = sA1d;            bjB = sB1d;            break;
                    case 3: bjA = cA0d;            bjB = cB0d;            break;
                    case 4: bjA = m2(cA0d, cA1d);  bjB = m2(cB0d, cB1d);  break;
                    case 5: bjA = m2(cA0d, sA1d);  bjB = m2(cB0d, sB1d);  break;
                    case 6: bjA = sA0d;            bjB = sB0d;            break;
                    case 7: bjA = m2(sA0d, cA1d);  bjB = m2(sB0d, cB1d);  break;
                    default: bjA = m2(sA0d, sA1d); bjB = m2(sB0d, sB1d);  break;
                }
                aA01 = f2(bjA, iA01, aA01);
                aA23 = f2(bjA, iA23, aA23);
                aB01 = f2(bjB, iB01, aB01);
                aB23 = f2(bjB, iB23, aB23);
            }
        }

        float4 oa, ob;
        upk(oa.x, oa.y, aA01); upk(oa.z, oa.w, aA23);
        upk(ob.x, ob.y, aB01); upk(ob.z, ob.w, aB23);
        out[2 * gid]     = oa;
        out[2 * gid + 1] = ob;
    }
}

// ============================================================================
extern "C" void kernel_launch(void* const* d_in, const int* in_sizes, int n_in,
                              void* d_out, int out_size)
{
    const float* x = (const float*)d_in[0];        // [B,4] float32
    const float* w = (const float*)d_in[1];        // [3,4,3] float32

    const int B = in_sizes[0] / 4;                 // 524288
    const int nPairs = B / 2;                      // 262144

    prep_kernel<<<1, NTHREADS>>>(w);
    qnat_main<<<NBLOCKS, NTHREADS>>>((const float4*)x, (float4*)d_out, nPairs);
}

// round 10
// speedup vs baseline: 6.2865x; 1.1579x over previous
#include <cuda_runtime.h>

// ============================================================================
// QuantumNAT: 4-qubit circuit, B=524288.  TWO KERNELS, ONE-SHOT MAIN.
// out_q(x) = sum_{t in {1,cos,sin}^4} D_q[t] * prod_i basis_i[t_i]
// prep_kernel: 1 block, computes D[81] as float4{D0,D1,D2,D3} -> g_coefStage.
// qnat_main:   ONE sample per thread, ONE-SHOT (grid = B/256 = 2048).
//              f32x2 packing across the two OUTPUT pairs {o0,o1},{o2,o3}.
//
// HARD-LEARNED RULE: no outer loops in the main kernel. Any grid-stride /
// fused loop makes ptxas software-pipeline across iterations and either
// balloon to 255 regs (R6/R9) or spill under a cap (R5/R7/R8). One-shot
// uncapped kernels allocate sanely (R4: 66 regs).
// ============================================================================

#define NTHREADS 256

__device__ float4 g_coefStage[81];

// ---------------- complex helpers (prep only) ----------------
__device__ __forceinline__ float2 cmul(float2 a, float2 b) {
    return make_float2(a.x * b.x - a.y * b.y, a.x * b.y + a.y * b.x);
}
__device__ __forceinline__ float2 cmulcj(float2 a, float2 b) {  // conj(a)*b
    return make_float2(a.x * b.x + a.y * b.y, a.x * b.y - a.y * b.x);
}
__device__ __forceinline__ float2 cadd(float2 a, float2 b) {
    return make_float2(a.x + b.x, a.y + b.y);
}
__device__ __forceinline__ float2 csub(float2 a, float2 b) {
    return make_float2(a.x - b.x, a.y - b.y);
}
__device__ __forceinline__ float2 ctr(float2 x00, float2 x01, float2 x10, float2 x11, int tsel) {
    if (tsel == 0) return make_float2(0.5f * (x00.x + x11.x), 0.5f * (x00.y + x11.y));
    if (tsel == 1) return make_float2(0.5f * (x00.x - x11.x), 0.5f * (x00.y - x11.y));
    return make_float2(0.5f * (x01.y - x10.y), 0.5f * (x10.x - x01.x));
}

// ============================================================================
// Prep kernel: one block, 256 threads (proven since R2).
// ============================================================================
__global__ void prep_kernel(const float* __restrict__ w)
{
    __shared__ float2 Ug[12][2][2];
    __shared__ float2 Wm[16][16];
    __shared__ float2 Mq[4][16][16];
    __shared__ float2 T3[4][3][8][8];
    __shared__ float2 T2s[4][3][3][4][4];
    __shared__ float2 T1s[4][3][3][3][2][2];

    const int t = threadIdx.x;

    if (t < 12) {
        float ax = 0.5f * w[t * 3 + 0];
        float ay = 0.5f * w[t * 3 + 1];
        float az = 0.5f * w[t * 3 + 2];
        float sx = sinf(ax), cx = cosf(ax);
        float sy = sinf(ay), cy = cosf(ay);
        float sz = sinf(az), cz = cosf(az);
        float2 a00 = make_float2( cy * cx,  sy * sx);
        float2 a01 = make_float2(-sy * cx, -cy * sx);
        float2 a10 = make_float2( sy * cx, -cy * sx);
        float2 a11 = make_float2( cy * cx, -sy * sx);
        float2 e0 = make_float2(cz, -sz);
        float2 e1 = make_float2(cz,  sz);
        Ug[t][0][0] = cmul(e0, a00); Ug[t][0][1] = cmul(e0, a01);
        Ug[t][1][0] = cmul(e1, a10); Ug[t][1][1] = cmul(e1, a11);
    }
    __syncthreads();

    if (t < 16) {
        float2 col[16];
        #pragma unroll
        for (int m = 0; m < 16; m++) col[m] = make_float2((m == t) ? 1.0f : 0.0f, 0.0f);

        #pragma unroll
        for (int l = 0; l < 3; l++) {
            #pragma unroll
            for (int i = 0; i < 4; i++) {
                float2 u00 = Ug[l * 4 + i][0][0], u01 = Ug[l * 4 + i][0][1];
                float2 u10 = Ug[l * 4 + i][1][0], u11 = Ug[l * 4 + i][1][1];
                const int str = 1 << (3 - i);
                #pragma unroll
                for (int p = 0; p < 8; p++) {
                    const int low = p & (str - 1);
                    const int m0  = ((p - low) << 1) | low;
                    const int m1  = m0 | str;
                    float2 a = col[m0], b = col[m1];
                    col[m0] = cadd(cmul(u00, a), cmul(u01, b));
                    col[m1] = cadd(cmul(u10, a), cmul(u11, b));
                }
            }
            #pragma unroll
            for (int i = 0; i < 3; i++) {
                const int cmask = 1 << (3 - i);
                const int tmask = 1 << (2 - i);
                #pragma unroll
                for (int m = 0; m < 16; m++) {
                    if ((m & cmask) && !(m & tmask)) {
                        float2 tmp = col[m];
                        col[m] = col[m | tmask];
                        col[m | tmask] = tmp;
                    }
                }
            }
        }
        #pragma unroll
        for (int m = 0; m < 16; m++) Wm[m][t] = col[m];
    }
    __syncthreads();

    {
        const int j = t >> 4, k = t & 15;
        float2 a0 = make_float2(0.f, 0.f), a1 = a0, a2 = a0, a3 = a0;
        #pragma unroll
        for (int m = 0; m < 16; m++) {
            float2 p = cmulcj(Wm[m][j], Wm[m][k]);
            a0 = (m & 8) ? csub(a0, p) : cadd(a0, p);
            a1 = (m & 4) ? csub(a1, p) : cadd(a1, p);
            a2 = (m & 2) ? csub(a2, p) : cadd(a2, p);
            a3 = (m & 1) ? csub(a3, p) : cadd(a3, p);
        }
        Mq[0][j][k] = a0; Mq[1][j][k] = a1; Mq[2][j][k] = a2; Mq[3][j][k] = a3;
    }
    __syncthreads();

    for (int e = t; e < 768; e += NTHREADS) {
        const int q = e / 192, r = e % 192, t3 = r / 64, ab = r % 64;
        const int a = ab >> 3, b = ab & 7;
        T3[q][t3][a][b] = ctr(Mq[q][2 * a][2 * b],     Mq[q][2 * a][2 * b + 1],
                              Mq[q][2 * a + 1][2 * b], Mq[q][2 * a + 1][2 * b + 1], t3);
    }
    __syncthreads();

    for (int e = t; e < 576; e += NTHREADS) {
        const int q = e / 144, r = e % 144, t2 = r / 48, r2 = r % 48;
        const int t3 = r2 / 16, ab = r2 % 16, a = ab >> 2, b = ab & 3;
        T2s[q][t2][t3][a][b] = ctr(T3[q][t3][2 * a][2 * b],     T3[q][t3][2 * a][2 * b + 1],
                                   T3[q][t3][2 * a + 1][2 * b], T3[q][t3][2 * a + 1][2 * b + 1], t2);
    }
    __syncthreads();

    for (int e = t; e < 432; e += NTHREADS) {
        const int q = e / 108, r = e % 108, t1 = r / 36, r2 = r % 36;
        const int t2 = r2 / 12, r3 = r2 % 12, t3 = r3 / 4, ab = r3 & 3;
        const int a = ab >> 1, b = ab & 1;
        T1s[q][t1][t2][t3][a][b] = ctr(T2s[q][t2][t3][2 * a][2 * b],     T2s[q][t2][t3][2 * a][2 * b + 1],
                                       T2s[q][t2][t3][2 * a + 1][2 * b], T2s[q][t2][t3][2 * a + 1][2 * b + 1], t1);
    }
    __syncthreads();

    for (int e = t; e < 324; e += NTHREADS) {
        const int q = e / 81, tt = e % 81;
        const int t0 = tt / 27, r = tt % 27, t1 = r / 9, r2 = r % 9, t2 = r2 / 3, t3 = r2 % 3;
        float2 x00 = T1s[q][t1][t2][t3][0][0];
        float2 x01 = T1s[q][t1][t2][t3][0][1];
        float2 x10 = T1s[q][t1][t2][t3][1][0];
        float2 x11 = T1s[q][t1][t2][t3][1][1];
        float d;
        if (t0 == 0)      d = 0.5f * (x00.x + x11.x);
        else if (t0 == 1) d = 0.5f * (x00.x - x11.x);
        else              d = 0.5f * (x01.y - x10.y);
        reinterpret_cast<float*>(g_coefStage)[tt * 4 + q] = d;
    }
}

// ---------------- packed f32x2 helpers ----------------
__device__ __forceinline__ unsigned long long pk(float a, float b) {
    unsigned long long r;
    asm("mov.b64 %0, {%1, %2};" : "=l"(r) : "f"(a), "f"(b));
    return r;
}
__device__ __forceinline__ void upk(float& a, float& b, unsigned long long v) {
    asm("mov.b64 {%0, %1}, %2;" : "=f"(a), "=f"(b) : "l"(v));
}
__device__ __forceinline__ unsigned long long m2(unsigned long long a, unsigned long long b) {
    unsigned long long r;
    asm("mul.rn.f32x2 %0, %1, %2;" : "=l"(r) : "l"(a), "l"(b));
    return r;
}
__device__ __forceinline__ unsigned long long f2(unsigned long long a, unsigned long long b,
                                                 unsigned long long c) {
    unsigned long long r;
    asm("fma.rn.f32x2 %0, %1, %2, %3;" : "=l"(r) : "l"(a), "l"(b), "l"(c));
    return r;
}

// ============================================================================
// Main kernel: ONE-SHOT, one sample per thread.  grid = B/256 = 2048.
// ============================================================================
__global__ __launch_bounds__(NTHREADS)
void qnat_main(const float4* __restrict__ x, float4* __restrict__ out)
{
    __shared__ ulonglong2 sc[81];   // {D0,D1},{D2,D3} per t-index
    if (threadIdx.x < 81)
        sc[threadIdx.x] = reinterpret_cast<const ulonglong2*>(g_coefStage)[threadIdx.x];
    __syncthreads();

    const int gid = blockIdx.x * NTHREADS + threadIdx.x;
    const float4 xv = x[gid];

    float s0, c0, s1, c1, s2, c2, s3, c3;
    __sincosf(xv.x, &s0, &c0);
    __sincosf(xv.y, &s1, &c1);
    __sincosf(xv.z, &s2, &c2);
    __sincosf(xv.w, &s3, &c3);

    // duplicated packed sincos values
    const unsigned long long c0d = pk(c0, c0), s0d = pk(s0, s0);
    const unsigned long long c1d = pk(c1, c1), s1d = pk(s1, s1);
    const unsigned long long c2d = pk(c2, c2), s2d = pk(s2, s2);
    const unsigned long long c3d = pk(c3, c3), s3d = pk(s3, s3);

    // b23 basis (qubits 2,3), duplicated. Index k = t2*3 + t3 (k=0 is 1).
    unsigned long long b[9];
    b[1] = c3d; b[2] = s3d; b[3] = c2d;
    b[4] = m2(c2d, c3d); b[5] = m2(c2d, s3d);
    b[6] = s2d; b[7] = m2(s2d, c3d); b[8] = m2(s2d, s3d);

    unsigned long long a01 = 0, a23 = 0;

    #pragma unroll
    for (int j = 0; j < 9; j++) {
        ulonglong2 cv0 = sc[j * 9];
        unsigned long long i01 = cv0.x, i23 = cv0.y;
        #pragma unroll
        for (int k = 1; k < 9; k++) {
            const ulonglong2 cv = sc[j * 9 + k];
            i01 = f2(cv.x, b[k], i01);
            i23 = f2(cv.y, b[k], i23);
        }
        if (j == 0) {
            a01 = i01; a23 = i23;
        } else {
            unsigned long long bj;
            switch (j) {
                case 1: bj = c1d;           break;
                case 2: bj = s1d;           break;
                case 3: bj = c0d;           break;
                case 4: bj = m2(c0d, c1d);  break;
                case 5: bj = m2(c0d, s1d);  break;
                case 6: bj = s0d;           break;
                case 7: bj = m2(s0d, c1d);  break;
                default: bj = m2(s0d, s1d); break;
            }
            a01 = f2(bj, i01, a01);
            a23 = f2(bj, i23, a23);
        }
    }

    float4 o;
    upk(o.x, o.y, a01);
    upk(o.z, o.w, a23);
    out[gid] = o;
}

// ============================================================================
extern "C" void kernel_launch(void* const* d_in, const int* in_sizes, int n_in,
                              void* d_out, int out_size)
{
    const float* x = (const float*)d_in[0];        // [B,4] float32
    const float* w = (const float*)d_in[1];        // [3,4,3] float32

    const int B = in_sizes[0] / 4;                 // 524288 samples
    const int grid = B / NTHREADS;                 // 2048 one-shot blocks

    prep_kernel<<<1, NTHREADS>>>(w);
    qnat_main<<<grid, NTHREADS>>>((const float4*)x, (float4*)d_out);
}

// round 11
// speedup vs baseline: 8.1132x; 1.2906x over previous
#include <cuda_runtime.h>

// ============================================================================
// QuantumNAT: 4-qubit circuit, B=524288.  TWO KERNELS, ONE-SHOT MAIN.
// out_q(x) = sum_{t in {1,cos,sin}^4} D_q[t] * prod_i basis_i[t_i]
// prep_kernel: 1 block/256 thr, computes D[81] float4{D0..D3} -> g_coefStage.
// qnat_main:   2 samples/thread (each coefficient LDS.128 feeds 4 packed
//              f32x2 FMAs), ONE-SHOT, block=128 -> 7 blocks/SM @ 66 regs
//              (28 warps/SM vs 24 at block=256).
//
// Hard-learned regalloc rules (R5-R9): no outer loop in the main kernel and
// no register caps — one-shot + uncapped is the only configuration where
// ptxas neither spills nor balloons for this body (66 regs, R4-proven).
// ============================================================================

#define PREP_THREADS 256
#define MAIN_THREADS 128

__device__ float4 g_coefStage[81];

// ---------------- complex helpers (prep only) ----------------
__device__ __forceinline__ float2 cmul(float2 a, float2 b) {
    return make_float2(a.x * b.x - a.y * b.y, a.x * b.y + a.y * b.x);
}
__device__ __forceinline__ float2 cmulcj(float2 a, float2 b) {  // conj(a)*b
    return make_float2(a.x * b.x + a.y * b.y, a.x * b.y - a.y * b.x);
}
__device__ __forceinline__ float2 cadd(float2 a, float2 b) {
    return make_float2(a.x + b.x, a.y + b.y);
}
__device__ __forceinline__ float2 csub(float2 a, float2 b) {
    return make_float2(a.x - b.x, a.y - b.y);
}
__device__ __forceinline__ float2 ctr(float2 x00, float2 x01, float2 x10, float2 x11, int tsel) {
    if (tsel == 0) return make_float2(0.5f * (x00.x + x11.x), 0.5f * (x00.y + x11.y));
    if (tsel == 1) return make_float2(0.5f * (x00.x - x11.x), 0.5f * (x00.y - x11.y));
    return make_float2(0.5f * (x01.y - x10.y), 0.5f * (x10.x - x01.x));
}

// ============================================================================
// Prep kernel: one block, 256 threads (proven since R2).
// ============================================================================
__global__ void prep_kernel(const float* __restrict__ w)
{
    __shared__ float2 Ug[12][2][2];
    __shared__ float2 Wm[16][16];
    __shared__ float2 Mq[4][16][16];
    __shared__ float2 T3[4][3][8][8];
    __shared__ float2 T2s[4][3][3][4][4];
    __shared__ float2 T1s[4][3][3][3][2][2];

    const int t = threadIdx.x;

    if (t < 12) {
        float ax = 0.5f * w[t * 3 + 0];
        float ay = 0.5f * w[t * 3 + 1];
        float az = 0.5f * w[t * 3 + 2];
        float sx = sinf(ax), cx = cosf(ax);
        float sy = sinf(ay), cy = cosf(ay);
        float sz = sinf(az), cz = cosf(az);
        float2 a00 = make_float2( cy * cx,  sy * sx);
        float2 a01 = make_float2(-sy * cx, -cy * sx);
        float2 a10 = make_float2( sy * cx, -cy * sx);
        float2 a11 = make_float2( cy * cx, -sy * sx);
        float2 e0 = make_float2(cz, -sz);
        float2 e1 = make_float2(cz,  sz);
        Ug[t][0][0] = cmul(e0, a00); Ug[t][0][1] = cmul(e0, a01);
        Ug[t][1][0] = cmul(e1, a10); Ug[t][1][1] = cmul(e1, a11);
    }
    __syncthreads();

    if (t < 16) {
        float2 col[16];
        #pragma unroll
        for (int m = 0; m < 16; m++) col[m] = make_float2((m == t) ? 1.0f : 0.0f, 0.0f);

        #pragma unroll
        for (int l = 0; l < 3; l++) {
            #pragma unroll
            for (int i = 0; i < 4; i++) {
                float2 u00 = Ug[l * 4 + i][0][0], u01 = Ug[l * 4 + i][0][1];
                float2 u10 = Ug[l * 4 + i][1][0], u11 = Ug[l * 4 + i][1][1];
                const int str = 1 << (3 - i);
                #pragma unroll
                for (int p = 0; p < 8; p++) {
                    const int low = p & (str - 1);
                    const int m0  = ((p - low) << 1) | low;
                    const int m1  = m0 | str;
                    float2 a = col[m0], b = col[m1];
                    col[m0] = cadd(cmul(u00, a), cmul(u01, b));
                    col[m1] = cadd(cmul(u10, a), cmul(u11, b));
                }
            }
            #pragma unroll
            for (int i = 0; i < 3; i++) {
                const int cmask = 1 << (3 - i);
                const int tmask = 1 << (2 - i);
                #pragma unroll
                for (int m = 0; m < 16; m++) {
                    if ((m & cmask) && !(m & tmask)) {
                        float2 tmp = col[m];
                        col[m] = col[m | tmask];
                        col[m | tmask] = tmp;
                    }
                }
            }
        }
        #pragma unroll
        for (int m = 0; m < 16; m++) Wm[m][t] = col[m];
    }
    __syncthreads();

    {
        const int j = t >> 4, k = t & 15;
        float2 a0 = make_float2(0.f, 0.f), a1 = a0, a2 = a0, a3 = a0;
        #pragma unroll
        for (int m = 0; m < 16; m++) {
            float2 p = cmulcj(Wm[m][j], Wm[m][k]);
            a0 = (m & 8) ? csub(a0, p) : cadd(a0, p);
            a1 = (m & 4) ? csub(a1, p) : cadd(a1, p);
            a2 = (m & 2) ? csub(a2, p) : cadd(a2, p);
            a3 = (m & 1) ? csub(a3, p) : cadd(a3, p);
        }
        Mq[0][j][k] = a0; Mq[1][j][k] = a1; Mq[2][j][k] = a2; Mq[3][j][k] = a3;
    }
    __syncthreads();

    for (int e = t; e < 768; e += PREP_THREADS) {
        const int q = e / 192, r = e % 192, t3 = r / 64, ab = r % 64;
        const int a = ab >> 3, b = ab & 7;
        T3[q][t3][a][b] = ctr(Mq[q][2 * a][2 * b],     Mq[q][2 * a][2 * b + 1],
                              Mq[q][2 * a + 1][2 * b], Mq[q][2 * a + 1][2 * b + 1], t3);
    }
    __syncthreads();

    for (int e = t; e < 576; e += PREP_THREADS) {
        const int q = e / 144, r = e % 144, t2 = r / 48, r2 = r % 48;
        const int t3 = r2 / 16, ab = r2 % 16, a = ab >> 2, b = ab & 3;
        T2s[q][t2][t3][a][b] = ctr(T3[q][t3][2 * a][2 * b],     T3[q][t3][2 * a][2 * b + 1],
                                   T3[q][t3][2 * a + 1][2 * b], T3[q][t3][2 * a + 1][2 * b + 1], t2);
    }
    __syncthreads();

    for (int e = t; e < 432; e += PREP_THREADS) {
        const int q = e / 108, r = e % 108, t1 = r / 36, r2 = r % 36;
        const int t2 = r2 / 12, r3 = r2 % 12, t3 = r3 / 4, ab = r3 & 3;
        const int a = ab >> 1, b = ab & 1;
        T1s[q][t1][t2][t3][a][b] = ctr(T2s[q][t2][t3][2 * a][2 * b],     T2s[q][t2][t3][2 * a][2 * b + 1],
                                       T2s[q][t2][t3][2 * a + 1][2 * b], T2s[q][t2][t3][2 * a + 1][2 * b + 1], t1);
    }
    __syncthreads();

    for (int e = t; e < 324; e += PREP_THREADS) {
        const int q = e / 81, tt = e % 81;
        const int t0 = tt / 27, r = tt % 27, t1 = r / 9, r2 = r % 9, t2 = r2 / 3, t3 = r2 % 3;
        float2 x00 = T1s[q][t1][t2][t3][0][0];
        float2 x01 = T1s[q][t1][t2][t3][0][1];
        float2 x10 = T1s[q][t1][t2][t3][1][0];
        float2 x11 = T1s[q][t1][t2][t3][1][1];
        float d;
        if (t0 == 0)      d = 0.5f * (x00.x + x11.x);
        else if (t0 == 1) d = 0.5f * (x00.x - x11.x);
        else              d = 0.5f * (x01.y - x10.y);
        reinterpret_cast<float*>(g_coefStage)[tt * 4 + q] = d;
    }
}

// ---------------- packed f32x2 helpers ----------------
__device__ __forceinline__ unsigned long long pk(float a, float b) {
    unsigned long long r;
    asm("mov.b64 %0, {%1, %2};" : "=l"(r) : "f"(a), "f"(b));
    return r;
}
__device__ __forceinline__ void upk(float& a, float& b, unsigned long long v) {
    asm("mov.b64 {%0, %1}, %2;" : "=f"(a), "=f"(b) : "l"(v));
}
__device__ __forceinline__ unsigned long long m2(unsigned long long a, unsigned long long b) {
    unsigned long long r;
    asm("mul.rn.f32x2 %0, %1, %2;" : "=l"(r) : "l"(a), "l"(b));
    return r;
}
__device__ __forceinline__ unsigned long long f2(unsigned long long a, unsigned long long b,
                                                 unsigned long long c) {
    unsigned long long r;
    asm("fma.rn.f32x2 %0, %1, %2, %3;" : "=l"(r) : "l"(a), "l"(b), "l"(c));
    return r;
}

// ============================================================================
// Main kernel: ONE-SHOT, 2 samples (1 pair) per thread, block = 128.
// grid = nPairs/128 = 2048.
// ============================================================================
__global__ __launch_bounds__(MAIN_THREADS)
void qnat_main(const float4* __restrict__ x, float4* __restrict__ out)
{
    __shared__ ulonglong2 sc[81];   // {D0,D1},{D2,D3} per t-index
    if (threadIdx.x < 81)
        sc[threadIdx.x] = reinterpret_cast<const ulonglong2*>(g_coefStage)[threadIdx.x];
    __syncthreads();

    const int gid = blockIdx.x * MAIN_THREADS + threadIdx.x;

    const float4 xa = x[2 * gid];
    const float4 xb = x[2 * gid + 1];

    float sA0, cA0, sA1, cA1, sA2, cA2, sA3, cA3;
    float sB0, cB0, sB1, cB1, sB2, cB2, sB3, cB3;
    __sincosf(xa.x, &sA0, &cA0);  __sincosf(xb.x, &sB0, &cB0);
    __sincosf(xa.y, &sA1, &cA1);  __sincosf(xb.y, &sB1, &cB1);
    __sincosf(xa.z, &sA2, &cA2);  __sincosf(xb.z, &sB2, &cB2);
    __sincosf(xa.w, &sA3, &cA3);  __sincosf(xb.w, &sB3, &cB3);

    const unsigned long long cA0d = pk(cA0, cA0), sA0d = pk(sA0, sA0);
    const unsigned long long cA1d = pk(cA1, cA1), sA1d = pk(sA1, sA1);
    const unsigned long long cA2d = pk(cA2, cA2), sA2d = pk(sA2, sA2);
    const unsigned long long cA3d = pk(cA3, cA3), sA3d = pk(sA3, sA3);
    const unsigned long long cB0d = pk(cB0, cB0), sB0d = pk(sB0, sB0);
    const unsigned long long cB1d = pk(cB1, cB1), sB1d = pk(sB1, sB1);
    const unsigned long long cB2d = pk(cB2, cB2), sB2d = pk(sB2, sB2);
    const unsigned long long cB3d = pk(cB3, cB3), sB3d = pk(sB3, sB3);

    // b23 basis (qubits 2,3), duplicated, per sample. Index k = t2*3 + t3.
    unsigned long long bA[9], bB[9];
    bA[1] = cA3d; bA[2] = sA3d; bA[3] = cA2d;
    bA[4] = m2(cA2d, cA3d); bA[5] = m2(cA2d, sA3d);
    bA[6] = sA2d; bA[7] = m2(sA2d, cA3d); bA[8] = m2(sA2d, sA3d);
    bB[1] = cB3d; bB[2] = sB3d; bB[3] = cB2d;
    bB[4] = m2(cB2d, cB3d); bB[5] = m2(cB2d, sB3d);
    bB[6] = sB2d; bB[7] = m2(sB2d, cB3d); bB[8] = m2(sB2d, sB3d);

    unsigned long long aA01 = 0, aA23 = 0, aB01 = 0, aB23 = 0;

    #pragma unroll
    for (int j = 0; j < 9; j++) {
        ulonglong2 cv0 = sc[j * 9];
        unsigned long long iA01 = cv0.x, iA23 = cv0.y;
        unsigned long long iB01 = cv0.x, iB23 = cv0.y;
        #pragma unroll
        for (int k = 1; k < 9; k++) {
            const ulonglong2 cv = sc[j * 9 + k];
            iA01 = f2(cv.x, bA[k], iA01);
            iA23 = f2(cv.y, bA[k], iA23);
            iB01 = f2(cv.x, bB[k], iB01);
            iB23 = f2(cv.y, bB[k], iB23);
        }
        if (j == 0) {
            aA01 = iA01; aA23 = iA23; aB01 = iB01; aB23 = iB23;
        } else {
            unsigned long long bjA, bjB;
            switch (j) {
                case 1: bjA = cA1d;            bjB = cB1d;            break;
                case 2: bjA = sA1d;            bjB = sB1d;            break;
                case 3: bjA = cA0d;            bjB = cB0d;            break;
                case 4: bjA = m2(cA0d, cA1d);  bjB = m2(cB0d, cB1d);  break;
                case 5: bjA = m2(cA0d, sA1d);  bjB = m2(cB0d, sB1d);  break;
                case 6: bjA = sA0d;            bjB = sB0d;            break;
                case 7: bjA = m2(sA0d, cA1d);  bjB = m2(sB0d, cB1d);  break;
                default: bjA = m2(sA0d, sA1d); bjB = m2(sB0d, sB1d);  break;
            }
            aA01 = f2(bjA, iA01, aA01);
            aA23 = f2(bjA, iA23, aA23);
            aB01 = f2(bjB, iB01, aB01);
            aB23 = f2(bjB, iB23, aB23);
        }
    }

    float4 oa, ob;
    upk(oa.x, oa.y, aA01); upk(oa.z, oa.w, aA23);
    upk(ob.x, ob.y, aB01); upk(ob.z, ob.w, aB23);
    out[2 * gid]     = oa;
    out[2 * gid + 1] = ob;
}

// ============================================================================
extern "C" void kernel_launch(void* const* d_in, const int* in_sizes, int n_in,
                              void* d_out, int out_size)
{
    const float* x = (const float*)d_in[0];        // [B,4] float32
    const float* w = (const float*)d_in[1];        // [3,4,3] float32

    const int B = in_sizes[0] / 4;                 // 524288 samples
    const int nPairs = B / 2;                      // 262144
    const int grid = nPairs / MAIN_THREADS;        // 2048 one-shot blocks

    prep_kernel<<<1, PREP_THREADS>>>(w);
    qnat_main<<<grid, MAIN_THREADS>>>((const float4*)x, (float4*)d_out);
}